// round 1
// baseline (speedup 1.0000x reference)
#include <cuda_runtime.h>
#include <cstdint>

#define N_NODES 65536
#define IN_FEAT 512
#define OUT_FEAT 256
#define N_REL 3
#define N_EDGES 500000
#define NEG_SLOPE 0.2f
#define EPS 1e-9f

// ---------------- scratch (static device globals; no allocs allowed) ---------
__device__ float    g_z[(size_t)N_NODES * OUT_FEAT];   // 64 MB, reused per relation
__device__ float    g_el[N_NODES];
__device__ float    g_er[N_NODES];
__device__ unsigned g_mord[N_NODES];                    // order-encoded float max
__device__ float    g_denom[N_NODES];
__device__ float    g_e[N_EDGES];                       // edge logits -> weights

// order-preserving float<->uint encoding (monotone, so atomicMax works)
__device__ __forceinline__ unsigned ford(float x) {
    unsigned u = __float_as_uint(x);
    return u ^ ((u >> 31) ? 0xFFFFFFFFu : 0x80000000u);
}
__device__ __forceinline__ float orf(unsigned u) {
    return __uint_as_float(u ^ ((u & 0x80000000u) ? 0x80000000u : 0xFFFFFFFFu));
}

// ---------------- init: out[n,f] = sum_r b[r][f] --------------------------
__global__ void init_out_kernel(const float* __restrict__ b, float* __restrict__ out) {
    int i = blockIdx.x * blockDim.x + threadIdx.x;
    if (i >= N_NODES * OUT_FEAT) return;
    int f = i & (OUT_FEAT - 1);
    out[i] = b[f] + b[OUT_FEAT + f] + b[2 * OUT_FEAT + f];
}

// ---------------- SGEMM: g_z = h @ W_r  (fp32, 128x128x8 tiles) ------------
#define BM 128
#define BN 128
#define BK 8
#define TM 8
#define TN 8

__global__ __launch_bounds__(256) void sgemm_kernel(const float* __restrict__ A,
                                                    const float* __restrict__ B) {
    __shared__ float As[BK][BM];
    __shared__ float Bs[BK][BN];
    const int bx = blockIdx.x;            // N tile (0..1)
    const int by = blockIdx.y;            // M tile (0..511)
    const int tid = threadIdx.x;
    const int tx = tid % 16, ty = tid / 16;

    const float* Ab = A + (size_t)by * BM * IN_FEAT;
    const float* Bb = B + bx * BN;

    float acc[TM][TN] = {};

    const int arow = tid >> 1;            // 0..127
    const int acol = (tid & 1) * 4;       // 0 or 4
    const int brow = tid >> 5;            // 0..7
    const int bcol = (tid & 31) * 4;      // 0..124

    for (int k0 = 0; k0 < IN_FEAT; k0 += BK) {
        float4 a4 = *(const float4*)(Ab + (size_t)arow * IN_FEAT + k0 + acol);
        As[acol + 0][arow] = a4.x;
        As[acol + 1][arow] = a4.y;
        As[acol + 2][arow] = a4.z;
        As[acol + 3][arow] = a4.w;
        float4 b4 = *(const float4*)(Bb + (size_t)(k0 + brow) * OUT_FEAT + bcol);
        *(float4*)&Bs[brow][bcol] = b4;
        __syncthreads();

        #pragma unroll
        for (int k = 0; k < BK; k++) {
            float ra[TM], rb[TN];
            float4 ra0 = *(const float4*)&As[k][ty * TM];
            float4 ra1 = *(const float4*)&As[k][ty * TM + 4];
            ra[0]=ra0.x; ra[1]=ra0.y; ra[2]=ra0.z; ra[3]=ra0.w;
            ra[4]=ra1.x; ra[5]=ra1.y; ra[6]=ra1.z; ra[7]=ra1.w;
            float4 rb0 = *(const float4*)&Bs[k][tx * TN];
            float4 rb1 = *(const float4*)&Bs[k][tx * TN + 4];
            rb[0]=rb0.x; rb[1]=rb0.y; rb[2]=rb0.z; rb[3]=rb0.w;
            rb[4]=rb1.x; rb[5]=rb1.y; rb[6]=rb1.z; rb[7]=rb1.w;
            #pragma unroll
            for (int i = 0; i < TM; i++)
                #pragma unroll
                for (int j = 0; j < TN; j++)
                    acc[i][j] = fmaf(ra[i], rb[j], acc[i][j]);
        }
        __syncthreads();
    }

    float* Cb = g_z + (size_t)(by * BM + ty * TM) * OUT_FEAT + bx * BN + tx * TN;
    #pragma unroll
    for (int i = 0; i < TM; i++) {
        *(float4*)(Cb + (size_t)i * OUT_FEAT + 0) =
            make_float4(acc[i][0], acc[i][1], acc[i][2], acc[i][3]);
        *(float4*)(Cb + (size_t)i * OUT_FEAT + 4) =
            make_float4(acc[i][4], acc[i][5], acc[i][6], acc[i][7]);
    }
}

// ---------------- per-node logits el/er + reset max/denom ------------------
__global__ __launch_bounds__(256) void lr_kernel(const float* __restrict__ al,
                                                 const float* __restrict__ ar) {
    int node = (blockIdx.x * blockDim.x + threadIdx.x) >> 5;
    int lane = threadIdx.x & 31;
    if (node >= N_NODES) return;
    const float4* zr = (const float4*)(g_z + (size_t)node * OUT_FEAT);
    const float4* alv = (const float4*)al;
    const float4* arv = (const float4*)ar;
    float sl = 0.f, sr = 0.f;
    #pragma unroll
    for (int i = 0; i < 2; i++) {
        float4 z4 = zr[lane + 32 * i];
        float4 a4 = alv[lane + 32 * i];
        float4 r4 = arv[lane + 32 * i];
        sl += z4.x * a4.x + z4.y * a4.y + z4.z * a4.z + z4.w * a4.w;
        sr += z4.x * r4.x + z4.y * r4.y + z4.z * r4.z + z4.w * r4.w;
    }
    #pragma unroll
    for (int o = 16; o; o >>= 1) {
        sl += __shfl_xor_sync(0xFFFFFFFFu, sl, o);
        sr += __shfl_xor_sync(0xFFFFFFFFu, sr, o);
    }
    if (lane == 0) {
        g_el[node] = sl;
        g_er[node] = sr;
        g_mord[node] = 0u;      // encodes "below -FLT_MAX"
        g_denom[node] = 0.f;
    }
}

// ---------------- edge pass 1: logit + segment max -------------------------
__global__ void edge_max_kernel(const int* __restrict__ src, const int* __restrict__ dst) {
    int i = blockIdx.x * blockDim.x + threadIdx.x;
    if (i >= N_EDGES) return;
    int s = src[i], d = dst[i];
    float e = g_el[s] + g_er[d];
    e = e >= 0.f ? e : NEG_SLOPE * e;
    g_e[i] = e;
    atomicMax(&g_mord[d], ford(e));
}

// ---------------- edge pass 2: exp + segment sum ---------------------------
__global__ void edge_exp_kernel(const int* __restrict__ dst) {
    int i = blockIdx.x * blockDim.x + threadIdx.x;
    if (i >= N_EDGES) return;
    int d = dst[i];
    float m = orf(g_mord[d]);
    float w = expf(g_e[i] - m);
    g_e[i] = w;
    atomicAdd(&g_denom[d], w);
}

// ---------------- edge pass 3: weighted scatter (warp per edge) ------------
__global__ __launch_bounds__(256) void edge_scatter_kernel(const int* __restrict__ src,
                                                           const int* __restrict__ dst,
                                                           float* __restrict__ out) {
    int e = (blockIdx.x * blockDim.x + threadIdx.x) >> 5;
    int lane = threadIdx.x & 31;
    if (e >= N_EDGES) return;
    int s = src[e], d = dst[e];
    float alpha = g_e[e] / (g_denom[d] + EPS);
    const float4* zp = (const float4*)(g_z + (size_t)s * OUT_FEAT);
    float* op = out + (size_t)d * OUT_FEAT;
    #pragma unroll
    for (int i = 0; i < 2; i++) {
        float4 z4 = zp[lane + 32 * i];
        float vx = alpha * z4.x, vy = alpha * z4.y, vz = alpha * z4.z, vw = alpha * z4.w;
        asm volatile("red.global.add.v4.f32 [%0], {%1,%2,%3,%4};"
                     :: "l"(op + 4 * (lane + 32 * i)),
                        "f"(vx), "f"(vy), "f"(vz), "f"(vw)
                     : "memory");
    }
}

// ---------------- launch ----------------------------------------------------
extern "C" void kernel_launch(void* const* d_in, const int* in_sizes, int n_in,
                              void* d_out, int out_size) {
    const float* h   = (const float*)d_in[0];
    const float* W   = (const float*)d_in[1];
    const float* al  = (const float*)d_in[2];
    const float* ar  = (const float*)d_in[3];
    const float* b   = (const float*)d_in[4];
    const int*   src = (const int*)d_in[5];
    const int*   dst = (const int*)d_in[6];
    float*       out = (float*)d_out;

    init_out_kernel<<<(N_NODES * OUT_FEAT + 255) / 256, 256>>>(b, out);

    for (int r = 0; r < N_REL; r++) {
        const float* Wr  = W  + (size_t)r * IN_FEAT * OUT_FEAT;
        const float* alr = al + (size_t)r * OUT_FEAT;
        const float* arr = ar + (size_t)r * OUT_FEAT;
        const int*   sr  = src + (size_t)r * N_EDGES;
        const int*   dr  = dst + (size_t)r * N_EDGES;

        dim3 gemm_grid(OUT_FEAT / BN, N_NODES / BM);   // (2, 512)
        sgemm_kernel<<<gemm_grid, 256>>>(h, Wr);

        lr_kernel<<<(N_NODES * 32) / 256, 256>>>(alr, arr);

        int eg = (N_EDGES + 255) / 256;
        edge_max_kernel<<<eg, 256>>>(sr, dr);
        edge_exp_kernel<<<eg, 256>>>(dr);

        int sg = ((size_t)N_EDGES * 32 + 255) / 256;
        edge_scatter_kernel<<<sg, 256>>>(sr, dr, out);
    }
}

// round 2
// speedup vs baseline: 2.1866x; 2.1866x over previous
#include <cuda_runtime.h>
#include <cstdint>

#define N_NODES 65536
#define IN_FEAT 512
#define OUT_FEAT 256
#define N_REL 3
#define N_EDGES 500000
#define NEG_SLOPE 0.2f
#define EPS 1e-9f

// ---------------- scratch (static device globals; no allocs allowed) ---------
__device__ float    g_z[(size_t)N_NODES * OUT_FEAT];   // 64 MB, reused per relation
__device__ float    g_el[N_NODES];
__device__ float    g_er[N_NODES];
__device__ unsigned g_mord[N_NODES];                    // order-encoded float max
__device__ float    g_denom[N_NODES];
__device__ float    g_e[N_EDGES];                       // edge logits -> weights

// order-preserving float<->uint encoding (monotone, so atomicMax works)
__device__ __forceinline__ unsigned ford(float x) {
    unsigned u = __float_as_uint(x);
    return u ^ ((u >> 31) ? 0xFFFFFFFFu : 0x80000000u);
}
__device__ __forceinline__ float orf(unsigned u) {
    return __uint_as_float(u ^ ((u & 0x80000000u) ? 0x80000000u : 0xFFFFFFFFu));
}

// ---------------- init: out[n,f] = sum_r b[r][f] --------------------------
__global__ void init_out_kernel(const float* __restrict__ b, float* __restrict__ out) {
    int i = blockIdx.x * blockDim.x + threadIdx.x;
    if (i >= N_NODES * OUT_FEAT) return;
    int f = i & (OUT_FEAT - 1);
    out[i] = b[f] + b[OUT_FEAT + f] + b[2 * OUT_FEAT + f];
}

// ---------------- TF32 tensor-core GEMM: g_z = h @ W_r ---------------------
// CTA tile 128x128x32, 8 warps (2x4), warp tile m64n32, mma.m16n8k8.tf32.
#define GBM 128
#define GBN 128
#define GBK 32
#define LDA 36               // padded floats per A smem row  (conflict-free ldmatrix)
#define LDB 136              // padded floats per B smem row  (conflict-free LDS)
#define A_STAGE (GBM * LDA)  // floats
#define B_STAGE (GBK * LDB)
#define STAGE_FLOATS (A_STAGE + B_STAGE)
#define GEMM_SMEM_BYTES (2 * STAGE_FLOATS * 4)

__device__ __forceinline__ uint32_t smem_u32(const void* p) {
    return (uint32_t)__cvta_generic_to_shared(p);
}
__device__ __forceinline__ void cp_async16(uint32_t saddr, const void* gaddr) {
    asm volatile("cp.async.cg.shared.global [%0], [%1], 16;" :: "r"(saddr), "l"(gaddr));
}
__device__ __forceinline__ uint32_t to_tf32(uint32_t x) {
    asm("cvt.rna.tf32.f32 %0, %0;" : "+r"(x));
    return x;
}

__global__ __launch_bounds__(256, 2) void gemm_tf32_kernel(const float* __restrict__ A,
                                                           const float* __restrict__ B) {
    extern __shared__ float smem[];
    const int tid  = threadIdx.x;
    const int bx   = blockIdx.x;   // N tile (0..1)
    const int by   = blockIdx.y;   // M tile (0..511)
    const int warp = tid >> 5, lane = tid & 31;
    const int wm = warp >> 2;      // 0..1
    const int wn = warp & 3;       // 0..3

    // per-lane ldmatrix address components (A fragments)
    const int a_row_off = (lane & 7) + ((lane >> 3) & 1) * 8;
    const int a_col_off = ((lane >> 4) & 1) * 4;
    // per-lane B fragment components
    const int b_k_off = lane & 3;
    const int b_n_off = lane >> 2;

    const float* Ag0 = A + (size_t)(by * GBM) * IN_FEAT;
    const float* Bg0 = B + bx * GBN;

    float acc[4][4][4];
    #pragma unroll
    for (int i = 0; i < 4; i++)
        #pragma unroll
        for (int j = 0; j < 4; j++)
            #pragma unroll
            for (int v = 0; v < 4; v++) acc[i][j][v] = 0.f;

    auto load_stage = [&](int kt, int s) {
        float* As = smem + s * STAGE_FLOATS;
        float* Bs = As + A_STAGE;
        const float* Ag = Ag0 + kt * GBK;
        const float* Bg = Bg0 + (size_t)(kt * GBK) * OUT_FEAT;
        #pragma unroll
        for (int i = 0; i < 4; i++) {
            int q = tid + i * 256;             // A: 128 rows x 8 chunks
            int r = q >> 3, c = q & 7;
            cp_async16(smem_u32(As + r * LDA + c * 4), Ag + (size_t)r * IN_FEAT + c * 4);
        }
        #pragma unroll
        for (int i = 0; i < 4; i++) {
            int q = tid + i * 256;             // B: 32 rows x 32 chunks
            int r = q >> 5, c = q & 31;
            cp_async16(smem_u32(Bs + r * LDB + c * 4), Bg + (size_t)r * OUT_FEAT + c * 4);
        }
    };

    load_stage(0, 0);
    asm volatile("cp.async.commit_group;");
    load_stage(1, 1);
    asm volatile("cp.async.commit_group;");

    const int KITERS = IN_FEAT / GBK;          // 16
    for (int kt = 0; kt < KITERS; kt++) {
        asm volatile("cp.async.wait_group 1;");
        __syncthreads();

        const int s = kt & 1;
        const float* As = smem + s * STAGE_FLOATS;
        const float* Bs = As + A_STAGE;

        #pragma unroll
        for (int k8 = 0; k8 < GBK / 8; k8++) {
            uint32_t a[4][4];
            #pragma unroll
            for (int i = 0; i < 4; i++) {
                const float* p = As + (wm * 64 + i * 16 + a_row_off) * LDA + k8 * 8 + a_col_off;
                uint32_t addr = smem_u32(p);
                asm volatile("ldmatrix.sync.aligned.m8n8.x4.shared.b16 {%0,%1,%2,%3}, [%4];"
                             : "=r"(a[i][0]), "=r"(a[i][1]), "=r"(a[i][2]), "=r"(a[i][3])
                             : "r"(addr));
                a[i][0] = to_tf32(a[i][0]); a[i][1] = to_tf32(a[i][1]);
                a[i][2] = to_tf32(a[i][2]); a[i][3] = to_tf32(a[i][3]);
            }
            uint32_t bf[4][2];
            #pragma unroll
            for (int j = 0; j < 4; j++) {
                const float* p = Bs + (k8 * 8 + b_k_off) * LDB + wn * 32 + j * 8 + b_n_off;
                bf[j][0] = to_tf32(__float_as_uint(p[0]));
                bf[j][1] = to_tf32(__float_as_uint(p[4 * LDB]));
            }
            #pragma unroll
            for (int i = 0; i < 4; i++)
                #pragma unroll
                for (int j = 0; j < 4; j++) {
                    asm volatile(
                        "mma.sync.aligned.m16n8k8.row.col.f32.tf32.tf32.f32 "
                        "{%0,%1,%2,%3}, {%4,%5,%6,%7}, {%8,%9}, {%0,%1,%2,%3};"
                        : "+f"(acc[i][j][0]), "+f"(acc[i][j][1]),
                          "+f"(acc[i][j][2]), "+f"(acc[i][j][3])
                        : "r"(a[i][0]), "r"(a[i][1]), "r"(a[i][2]), "r"(a[i][3]),
                          "r"(bf[j][0]), "r"(bf[j][1]));
                }
        }
        __syncthreads();
        if (kt + 2 < KITERS) load_stage(kt + 2, s);
        asm volatile("cp.async.commit_group;");
    }

    // epilogue: write to g_z
    const int row0 = by * GBM + wm * 64;
    const int col0 = bx * GBN + wn * 32;
    const int gr = lane >> 2;
    const int gc = (lane & 3) * 2;
    #pragma unroll
    for (int i = 0; i < 4; i++) {
        float* r0p = g_z + (size_t)(row0 + i * 16 + gr) * OUT_FEAT + col0 + gc;
        float* r1p = r0p + (size_t)8 * OUT_FEAT;
        #pragma unroll
        for (int j = 0; j < 4; j++) {
            *(float2*)(r0p + j * 8) = make_float2(acc[i][j][0], acc[i][j][1]);
            *(float2*)(r1p + j * 8) = make_float2(acc[i][j][2], acc[i][j][3]);
        }
    }
}

// ---------------- per-node logits el/er + reset max/denom ------------------
__global__ __launch_bounds__(256) void lr_kernel(const float* __restrict__ al,
                                                 const float* __restrict__ ar) {
    int node = (blockIdx.x * blockDim.x + threadIdx.x) >> 5;
    int lane = threadIdx.x & 31;
    if (node >= N_NODES) return;
    const float4* zr = (const float4*)(g_z + (size_t)node * OUT_FEAT);
    const float4* alv = (const float4*)al;
    const float4* arv = (const float4*)ar;
    float sl = 0.f, sr = 0.f;
    #pragma unroll
    for (int i = 0; i < 2; i++) {
        float4 z4 = zr[lane + 32 * i];
        float4 a4 = alv[lane + 32 * i];
        float4 r4 = arv[lane + 32 * i];
        sl += z4.x * a4.x + z4.y * a4.y + z4.z * a4.z + z4.w * a4.w;
        sr += z4.x * r4.x + z4.y * r4.y + z4.z * r4.z + z4.w * r4.w;
    }
    #pragma unroll
    for (int o = 16; o; o >>= 1) {
        sl += __shfl_xor_sync(0xFFFFFFFFu, sl, o);
        sr += __shfl_xor_sync(0xFFFFFFFFu, sr, o);
    }
    if (lane == 0) {
        g_el[node] = sl;
        g_er[node] = sr;
        g_mord[node] = 0u;      // encodes "below -FLT_MAX"
        g_denom[node] = 0.f;
    }
}

// ---------------- edge pass 1: logit + segment max -------------------------
__global__ void edge_max_kernel(const int* __restrict__ src, const int* __restrict__ dst) {
    int i = blockIdx.x * blockDim.x + threadIdx.x;
    if (i >= N_EDGES) return;
    int s = src[i], d = dst[i];
    float e = g_el[s] + g_er[d];
    e = e >= 0.f ? e : NEG_SLOPE * e;
    g_e[i] = e;
    atomicMax(&g_mord[d], ford(e));
}

// ---------------- edge pass 2: exp + segment sum ---------------------------
__global__ void edge_exp_kernel(const int* __restrict__ dst) {
    int i = blockIdx.x * blockDim.x + threadIdx.x;
    if (i >= N_EDGES) return;
    int d = dst[i];
    float m = orf(g_mord[d]);
    float w = expf(g_e[i] - m);
    g_e[i] = w;
    atomicAdd(&g_denom[d], w);
}

// ---------------- edge pass 3: weighted scatter (warp per edge) ------------
__global__ __launch_bounds__(256) void edge_scatter_kernel(const int* __restrict__ src,
                                                           const int* __restrict__ dst,
                                                           float* __restrict__ out) {
    int e = (blockIdx.x * blockDim.x + threadIdx.x) >> 5;
    int lane = threadIdx.x & 31;
    if (e >= N_EDGES) return;
    int s = src[e], d = dst[e];
    float alpha = g_e[e] / (g_denom[d] + EPS);
    const float4* zp = (const float4*)(g_z + (size_t)s * OUT_FEAT);
    float* op = out + (size_t)d * OUT_FEAT;
    #pragma unroll
    for (int i = 0; i < 2; i++) {
        float4 z4 = zp[lane + 32 * i];
        float vx = alpha * z4.x, vy = alpha * z4.y, vz = alpha * z4.z, vw = alpha * z4.w;
        asm volatile("red.global.add.v4.f32 [%0], {%1,%2,%3,%4};"
                     :: "l"(op + 4 * (lane + 32 * i)),
                        "f"(vx), "f"(vy), "f"(vz), "f"(vw)
                     : "memory");
    }
}

// ---------------- launch ----------------------------------------------------
extern "C" void kernel_launch(void* const* d_in, const int* in_sizes, int n_in,
                              void* d_out, int out_size) {
    const float* h   = (const float*)d_in[0];
    const float* W   = (const float*)d_in[1];
    const float* al  = (const float*)d_in[2];
    const float* ar  = (const float*)d_in[3];
    const float* b   = (const float*)d_in[4];
    const int*   src = (const int*)d_in[5];
    const int*   dst = (const int*)d_in[6];
    float*       out = (float*)d_out;

    cudaFuncSetAttribute(gemm_tf32_kernel,
                         cudaFuncAttributeMaxDynamicSharedMemorySize, GEMM_SMEM_BYTES);

    init_out_kernel<<<(N_NODES * OUT_FEAT + 255) / 256, 256>>>(b, out);

    for (int r = 0; r < N_REL; r++) {
        const float* Wr  = W  + (size_t)r * IN_FEAT * OUT_FEAT;
        const float* alr = al + (size_t)r * OUT_FEAT;
        const float* arr = ar + (size_t)r * OUT_FEAT;
        const int*   sr  = src + (size_t)r * N_EDGES;
        const int*   dr  = dst + (size_t)r * N_EDGES;

        dim3 gemm_grid(OUT_FEAT / GBN, N_NODES / GBM);   // (2, 512)
        gemm_tf32_kernel<<<gemm_grid, 256, GEMM_SMEM_BYTES>>>(h, Wr);

        lr_kernel<<<(N_NODES * 32) / 256, 256>>>(alr, arr);

        int eg = (N_EDGES + 255) / 256;
        edge_max_kernel<<<eg, 256>>>(sr, dr);
        edge_exp_kernel<<<eg, 256>>>(dr);

        int sg = ((size_t)N_EDGES * 32 + 255) / 256;
        edge_scatter_kernel<<<sg, 256>>>(sr, dr, out);
    }
}